// round 15
// baseline (speedup 1.0000x reference)
#include <cuda_runtime.h>
#include <cuda_pipeline.h>
#include <cuda_fp16.h>
#include <mma.h>
#include <math.h>
#include <stdint.h>

using namespace nvcuda;

#define NTOK 8192
#define HID 2048
#define FFN 8192
#define NHEAD 16
#define DHEAD 128
#define QKVW (3 * HID)
#define K2 (2 * HID)
#define SZ_HH ((size_t)HID * HID)
#define SZ_NH ((size_t)NTOK * HID)
#define SZ_HF ((size_t)HID * FFN)
#define SZ_NF ((size_t)NTOK * FFN)

// ---------------- scratch (__device__ globals; no allocation) --------------
__device__ __half h_TPw[(size_t)NTOK * K2];                 // [t0 | t1] K-concat
__device__ __half h_Epk[SZ_NH], h_Opk[SZ_NH], h_TP[SZ_NH], h_Dp[SZ_NH], h_F1[SZ_NF];
__device__ __half h_w0[SZ_HH], h_w2[SZ_HH], h_w4[SZ_HH], h_w5[SZ_HH], h_w9[SZ_HH];
__device__ __half h_wqkv[3 * SZ_HH], h_wpd[(size_t)HID * K2];  // [pw2; -ow2] packed
__device__ __half h_wf1[SZ_HF], h_wf2[SZ_HF];
__device__ float g_Rw[SZ_NH], g_X1[SZ_NH], g_QKV[(size_t)NTOK * QKVW];
__device__ float g_bqkv[QKVW], g_bd[HID];

// ---------------- pack kernels (exactly 3 launches before first GEMM) ------
// W [Kd][Nd] fp32 (row stride Nd) -> out[(n)*ldk + koff + k] = scale * W[k][n]
__device__ __forceinline__ void pack_b_body(const float* __restrict__ W,
                                            __half* __restrict__ out, int Nd,
                                            int ldk, int koff, float scale,
                                            int kblk, int nblk) {
    __shared__ float s[32][65];
    const int k0 = kblk * 32, n0 = nblk * 64, t = threadIdx.x;
    #pragma unroll
    for (int i = 0; i < 8; i++) {
        int idx = t + i * 256, k = idx >> 6, n = idx & 63;
        s[k][n] = W[(size_t)(k0 + k) * Nd + n0 + n] * scale;
    }
    __syncthreads();
    #pragma unroll
    for (int i = 0; i < 2; i++) {
        int u = t + i * 256, n = u >> 3, kg = u & 7;
        __half2 h0 = __floats2half2_rn(s[kg * 4 + 0][n], s[kg * 4 + 1][n]);
        __half2 h1 = __floats2half2_rn(s[kg * 4 + 2][n], s[kg * 4 + 3][n]);
        *(uint2*)(out + (size_t)(n0 + n) * ldk + koff + k0 + kg * 4) =
            make_uint2(*(uint32_t*)&h0, *(uint32_t*)&h1);
    }
}
struct PackB10 { const float* s[10]; __half* d[10]; int ldk[10]; int koff[10]; float sc[10]; };
__global__ void pack_bh10(PackB10 p) {                 // launch 1: 10 HxH weights
    int z = blockIdx.z;
    pack_b_body(p.s[z], p.d[z], HID, p.ldk[z], p.koff[z], p.sc[z],
                blockIdx.x, blockIdx.y);
}
struct PackBF { const float* s[2]; __half* d[2]; };
__global__ void pack_bhffn(PackBF p) {                 // launch 2: fw1 + fw2, exact count
    int bid = blockIdx.x;
    if (bid < 8192) {        // fw1 [HID][FFN] -> [FFN][HID]: 64 kblk x 128 nblk
        pack_b_body(p.s[0], p.d[0], FFN, HID, 0, 1.0f, bid & 63, bid >> 6);
    } else {                 // fw2 [FFN][HID] -> [HID][FFN]: 256 kblk x 32 nblk
        int b = bid - 8192;
        pack_b_body(p.s[1], p.d[1], HID, FFN, 0, 1.0f, b & 255, b >> 8);
    }
}
struct PackMisc { const float* e; const float* o; __half* ep; __half* op;
                  const float* b0; const float* b1; const float* b2; float* bq;
                  const float* pb2; const float* ob2; float* bd; };
__global__ void pack_misc(PackMisc p) {                // launch 3: inputs fp16 + biases
    if (blockIdx.z < 2) {
        size_t u = ((size_t)blockIdx.x * 256 + threadIdx.x) * 4;
        const float* X = blockIdx.z ? p.o : p.e;
        __half* out = blockIdx.z ? p.op : p.ep;
        float4 v = *(const float4*)(X + u);
        __half2 h0 = __floats2half2_rn(v.x, v.y);
        __half2 h1 = __floats2half2_rn(v.z, v.w);
        *(uint2*)(out + u) = make_uint2(*(uint32_t*)&h0, *(uint32_t*)&h1);
    } else {
        int i = blockIdx.x * 256 + threadIdx.x;
        if (i < QKVW)
            p.bq[i] = (i < HID) ? p.b0[i] : (i < 2 * HID) ? p.b1[i - HID] : p.b2[i - 2 * HID];
        else if (i < QKVW + HID)
            p.bd[i - QKVW] = p.pb2[i - QKVW] - p.ob2[i - QKVW];
    }
}

// ---- fp16 wmma GEMM, 64x128 tile, 128 thr (4 warps, 32x64 warp tile),
// ---- 4 CTAs/SM for 4 independent barrier domains. BK=32, 3-stage cp.async.
// A [M][Kd] fp16 row-major, Bm [Nd][Kd] fp16 (B^T), C = epi(A@B + bias)
// EPI: 0 bias, 1 relu, 2 leaky(0.01), 3 extra - x, 4 x + extra.  OPK: fp16 out.
#define BM 64
#define BN 128
#define BK 32
#define STG 3
#define ROWH 40
#define ASTG (BM * ROWH)
#define BSTG (BN * ROWH)
#define GEMM_SMEM ((ASTG + BSTG) * STG * 2)

template<int EPI, bool OPK>
__global__ void __launch_bounds__(128, 4) gemm_h(
    const __half* __restrict__ A, const __half* __restrict__ Bm,
    const float* __restrict__ bias, const float* __restrict__ extra,
    void* __restrict__ Cv, int Kd, int ldc, int lde)
{
    extern __shared__ char smem[];
    __half* sA = (__half*)smem;
    __half* sB = sA + STG * ASTG;
    float*  sEp = (float*)smem;   // epilogue alias (after final sync)

    const int t = threadIdx.x, warp = t >> 5, lane = t & 31;
    const int bn = blockIdx.x, bm = blockIdx.y;
    const int wm = warp & 1, wn = warp >> 1;       // 2x2 warp grid, warp tile 32x64
    const int KT = Kd / BK;
    const __half* Ab = A + (size_t)bm * BM * Kd;
    const __half* Bb = Bm + (size_t)bn * BN * Kd;

    wmma::fragment<wmma::accumulator, 16, 16, 16, float> acc[2][4];
    #pragma unroll
    for (int i = 0; i < 2; i++)
        #pragma unroll
        for (int j = 0; j < 4; j++)
            wmma::fill_fragment(acc[i][j], 0.0f);

    auto load_tile = [&](int kt, int stg) {
        #pragma unroll
        for (int i = 0; i < 2; i++) {   // A: 64 rows x 4 chunks of 16B = 256
            int c = t + i * 128, r = c >> 2, ch = c & 3;
            __pipeline_memcpy_async(sA + stg * ASTG + r * ROWH + ch * 8,
                                    Ab + (size_t)r * Kd + kt * BK + ch * 8, 16);
        }
        #pragma unroll
        for (int i = 0; i < 4; i++) {   // B: 128 rows x 4 chunks = 512
            int c = t + i * 128, r = c >> 2, ch = c & 3;
            __pipeline_memcpy_async(sB + stg * BSTG + r * ROWH + ch * 8,
                                    Bb + (size_t)r * Kd + kt * BK + ch * 8, 16);
        }
    };

    load_tile(0, 0); __pipeline_commit();
    load_tile(1, 1); __pipeline_commit();

    for (int kt = 0; kt < KT; ++kt) {
        __pipeline_wait_prior(1);
        __syncthreads();
        const int s = kt % STG;
        const __half* pA = sA + s * ASTG;
        const __half* pB = sB + s * BSTG;
        #pragma unroll
        for (int ks = 0; ks < 2; ++ks) {
            wmma::fragment<wmma::matrix_a, 16, 16, 16, __half, wmma::row_major> af[2];
            wmma::fragment<wmma::matrix_b, 16, 16, 16, __half, wmma::col_major> bf[4];
            #pragma unroll
            for (int fm = 0; fm < 2; ++fm)
                wmma::load_matrix_sync(af[fm], pA + (wm * 32 + fm * 16) * ROWH + ks * 16, ROWH);
            #pragma unroll
            for (int fn = 0; fn < 4; ++fn)
                wmma::load_matrix_sync(bf[fn], pB + (wn * 64 + fn * 16) * ROWH + ks * 16, ROWH);
            #pragma unroll
            for (int fm = 0; fm < 2; ++fm)
                #pragma unroll
                for (int fn = 0; fn < 4; ++fn)
                    wmma::mma_sync(acc[fm][fn], af[fm], bf[fn], acc[fm][fn]);
        }
        if (kt + 2 < KT) load_tile(kt + 2, (kt + 2) % STG);
        __pipeline_commit();
    }
    __syncthreads();

    // vectorized epilogue via per-warp smem scratch
    const size_t row0 = (size_t)bm * BM;
    const int    col0 = bn * BN;
    const int erow = lane >> 1, ecol = (lane & 1) * 8;
    #pragma unroll
    for (int fm = 0; fm < 2; ++fm) {
        #pragma unroll
        for (int fn = 0; fn < 4; ++fn) {
            wmma::store_matrix_sync(&sEp[warp * 256], acc[fm][fn], 16, wmma::mem_row_major);
            __syncwarp();
            const size_t gr = row0 + wm * 32 + fm * 16 + erow;
            const int    gc = col0 + wn * 64 + fn * 16 + ecol;
            float4 v0 = *(float4*)&sEp[warp * 256 + erow * 16 + ecol];
            float4 v1 = *(float4*)&sEp[warp * 256 + erow * 16 + ecol + 4];
            float4 b0 = *(const float4*)(bias + gc);
            float4 b1 = *(const float4*)(bias + gc + 4);
            float x[8] = { v0.x + b0.x, v0.y + b0.y, v0.z + b0.z, v0.w + b0.w,
                           v1.x + b1.x, v1.y + b1.y, v1.z + b1.z, v1.w + b1.w };
            if (EPI == 1) {
                #pragma unroll
                for (int q = 0; q < 8; q++) x[q] = fmaxf(x[q], 0.0f);
            } else if (EPI == 2) {
                #pragma unroll
                for (int q = 0; q < 8; q++) x[q] = (x[q] >= 0.f) ? x[q] : 0.01f * x[q];
            } else if (EPI == 3 || EPI == 4) {
                float4 e0 = *(const float4*)(extra + gr * (size_t)lde + gc);
                float4 e1 = *(const float4*)(extra + gr * (size_t)lde + gc + 4);
                float ev[8] = { e0.x, e0.y, e0.z, e0.w, e1.x, e1.y, e1.z, e1.w };
                #pragma unroll
                for (int q = 0; q < 8; q++)
                    x[q] = (EPI == 3) ? (ev[q] - x[q]) : (x[q] + ev[q]);
            }
            if (OPK) {
                __half2 p0 = __floats2half2_rn(x[0], x[1]), p1 = __floats2half2_rn(x[2], x[3]);
                __half2 p2 = __floats2half2_rn(x[4], x[5]), p3 = __floats2half2_rn(x[6], x[7]);
                *(uint4*)((__half*)Cv + gr * (size_t)ldc + gc) =
                    make_uint4(*(uint32_t*)&p0, *(uint32_t*)&p1, *(uint32_t*)&p2, *(uint32_t*)&p3);
            } else {
                float* cp = (float*)Cv + gr * (size_t)ldc + gc;
                *(float4*)cp       = make_float4(x[0], x[1], x[2], x[3]);
                *(float4*)(cp + 4) = make_float4(x[4], x[5], x[6], x[7]);
            }
            __syncwarp();
        }
    }
}

// ---------------- per-token head-vs-head attention (exact fp32) ------------
// QKV fused buffer: row stride 6144, Q at +0, K at +2048, V at +4096
__global__ void __launch_bounds__(128) attn_kernel(
    const float* __restrict__ QKV, const float* __restrict__ R,
    __half* __restrict__ outp)
{
    __shared__ __align__(16) float sQ[NHEAD][DHEAD], sK[NHEAD][DHEAD],
                                   sV[NHEAD][DHEAD], sR[NHEAD][DHEAD];
    const int n = blockIdx.x, t = threadIdx.x;
    const size_t b6 = (size_t)n * QKVW, base = (size_t)n * HID;
    #pragma unroll
    for (int i = t; i < HID / 4; i += 128) {
        ((float4*)sQ)[i] = ((const float4*)(QKV + b6))[i];
        ((float4*)sK)[i] = ((const float4*)(QKV + b6 + HID))[i];
        ((float4*)sV)[i] = ((const float4*)(QKV + b6 + 2 * HID))[i];
        ((float4*)sR)[i] = ((const float4*)(R + base))[i];
    }
    __syncthreads();
    const int warp = t >> 5, lane = t & 31;
    const float scale = 0.08838834764831845f;
    #pragma unroll
    for (int hh = 0; hh < 4; ++hh) {
        const int h = warp * 4 + hh;
        const float q0 = sQ[h][lane], q1 = sQ[h][lane + 32],
                    q2 = sQ[h][lane + 64], q3 = sQ[h][lane + 96];
        float sc[NHEAD];
        #pragma unroll
        for (int g = 0; g < NHEAD; ++g) {
            float s1 = q0 * sK[g][lane] + q1 * sK[g][lane + 32]
                     + q2 * sK[g][lane + 64] + q3 * sK[g][lane + 96];
            float s2 = q0 * sR[g][lane] + q1 * sR[g][lane + 32]
                     + q2 * sR[g][lane + 64] + q3 * sR[g][lane + 96];
            float v = s1 * scale - s2;
            #pragma unroll
            for (int o = 16; o > 0; o >>= 1) v += __shfl_xor_sync(0xffffffffu, v, o);
            sc[g] = v;
        }
        float m = sc[0];
        #pragma unroll
        for (int g = 1; g < NHEAD; ++g) m = fmaxf(m, sc[g]);
        float den = 0.f;
        #pragma unroll
        for (int g = 0; g < NHEAD; ++g) { sc[g] = expf(sc[g] - m); den += sc[g]; }
        const float inv = 1.0f / den;
        float o0 = 0, o1 = 0, o2 = 0, o3 = 0;
        #pragma unroll
        for (int g = 0; g < NHEAD; ++g) {
            float p = sc[g] * inv;
            o0 += p * sV[g][lane];      o1 += p * sV[g][lane + 32];
            o2 += p * sV[g][lane + 64]; o3 += p * sV[g][lane + 96];
        }
        __half* op = outp + base + (size_t)h * DHEAD;
        op[lane]      = __float2half_rn(o0);
        op[lane + 32] = __float2half_rn(o1);
        op[lane + 64] = __float2half_rn(o2);
        op[lane + 96] = __float2half_rn(o3);
    }
}

// ---------------- layernorm; optional fp16 copy ----------------------------
template<bool PK2>
__global__ void __launch_bounds__(256) ln_kernel(
    const float* __restrict__ x, const float* __restrict__ gamma,
    const float* __restrict__ beta, float* __restrict__ outr,
    __half* __restrict__ outp)
{
    __shared__ float sh[8];
    const int row = blockIdx.x, t = threadIdx.x, lane = t & 31, w = t >> 5;
    const float4* xr = (const float4*)(x + (size_t)row * HID);
    float4 a = xr[t], b = xr[t + 256];
    float s = a.x + a.y + a.z + a.w + b.x + b.y + b.z + b.w;
    #pragma unroll
    for (int o = 16; o > 0; o >>= 1) s += __shfl_xor_sync(0xffffffffu, s, o);
    if (lane == 0) sh[w] = s;
    __syncthreads();
    float tot = 0;
    #pragma unroll
    for (int i = 0; i < 8; i++) tot += sh[i];
    const float mean = tot * (1.0f / HID);
    float d, sq = 0;
    d = a.x - mean; sq += d * d; d = a.y - mean; sq += d * d;
    d = a.z - mean; sq += d * d; d = a.w - mean; sq += d * d;
    d = b.x - mean; sq += d * d; d = b.y - mean; sq += d * d;
    d = b.z - mean; sq += d * d; d = b.w - mean; sq += d * d;
    __syncthreads();
    #pragma unroll
    for (int o = 16; o > 0; o >>= 1) sq += __shfl_xor_sync(0xffffffffu, sq, o);
    if (lane == 0) sh[w] = sq;
    __syncthreads();
    tot = 0;
    #pragma unroll
    for (int i = 0; i < 8; i++) tot += sh[i];
    const float rstd = rsqrtf(tot * (1.0f / HID) + 1e-5f);
    float4 g0 = ((const float4*)gamma)[t], gA = ((const float4*)gamma)[t + 256];
    float4 e0 = ((const float4*)beta)[t],  eA = ((const float4*)beta)[t + 256];
    float4 r0 = make_float4((a.x - mean) * rstd * g0.x + e0.x, (a.y - mean) * rstd * g0.y + e0.y,
                            (a.z - mean) * rstd * g0.z + e0.z, (a.w - mean) * rstd * g0.w + e0.w);
    float4 r1 = make_float4((b.x - mean) * rstd * gA.x + eA.x, (b.y - mean) * rstd * gA.y + eA.y,
                            (b.z - mean) * rstd * gA.z + eA.z, (b.w - mean) * rstd * gA.w + eA.w);
    float4* o4 = (float4*)(outr + (size_t)row * HID);
    o4[t] = r0; o4[t + 256] = r1;
    if (PK2) {
        __half2 p0 = __floats2half2_rn(r0.x, r0.y), p1 = __floats2half2_rn(r0.z, r0.w);
        __half2 p2 = __floats2half2_rn(r1.x, r1.y), p3 = __floats2half2_rn(r1.z, r1.w);
        __half* op = outp + (size_t)row * HID;
        *(uint2*)(op + t * 4)        = make_uint2(*(uint32_t*)&p0, *(uint32_t*)&p1);
        *(uint2*)(op + t * 4 + 1024) = make_uint2(*(uint32_t*)&p2, *(uint32_t*)&p3);
    }
}

// ---------------- host ------------------------------------------------------
template<int EPI, bool OPK>
static void G(const __half* A, const __half* B, const float* bias, const float* extra,
              void* C, int Nd, int Kd, int ldc, int lde)
{
    cudaFuncSetAttribute(gemm_h<EPI, OPK>, cudaFuncAttributeMaxDynamicSharedMemorySize, GEMM_SMEM);
    gemm_h<EPI, OPK><<<dim3(Nd / BN, NTOK / BM), 128, GEMM_SMEM>>>(
        A, B, bias, extra, C, Kd, ldc, lde);
}

extern "C" void kernel_launch(void* const* d_in, const int* in_sizes, int n_in,
                              void* d_out, int out_size)
{
    const float* in[30];
    for (int i = 0; i < 30; i++) in[i] = (const float*)d_in[i];
    const float *E = in[0], *Obs = in[1];
    float* out = (float*)d_out;

    __half *TPw, *Epk, *Opk, *TP, *Dp, *F1;
    __half *W0, *W2, *W4, *W5, *W9, *Wqkv, *Wpd, *Wf1, *Wf2;
    float *Rw, *X1, *QKV, *bqkv, *bd;
    cudaGetSymbolAddress((void**)&TPw, h_TPw);
    cudaGetSymbolAddress((void**)&Epk, h_Epk); cudaGetSymbolAddress((void**)&Opk, h_Opk);
    cudaGetSymbolAddress((void**)&TP,  h_TP);  cudaGetSymbolAddress((void**)&Dp,  h_Dp);
    cudaGetSymbolAddress((void**)&F1,  h_F1);
    cudaGetSymbolAddress((void**)&W0, h_w0);   cudaGetSymbolAddress((void**)&W2, h_w2);
    cudaGetSymbolAddress((void**)&W4, h_w4);   cudaGetSymbolAddress((void**)&W5, h_w5);
    cudaGetSymbolAddress((void**)&W9, h_w9);   cudaGetSymbolAddress((void**)&Wqkv, h_wqkv);
    cudaGetSymbolAddress((void**)&Wpd, h_wpd);
    cudaGetSymbolAddress((void**)&Wf1, h_wf1); cudaGetSymbolAddress((void**)&Wf2, h_wf2);
    cudaGetSymbolAddress((void**)&Rw, g_Rw);   cudaGetSymbolAddress((void**)&X1, g_X1);
    cudaGetSymbolAddress((void**)&QKV, g_QKV); cudaGetSymbolAddress((void**)&bqkv, g_bqkv);
    cudaGetSymbolAddress((void**)&bd, g_bd);

    // ---- launch 1: 10 HxH weight packs (pw2/ow2 go K-concatenated into Wpd) ----
    PackB10 pb;
    auto set = [&](int i, const float* s, __half* d, int ldk, int koff, float sc) {
        pb.s[i] = s; pb.d[i] = d; pb.ldk[i] = ldk; pb.koff[i] = koff; pb.sc[i] = sc;
    };
    set(0, in[2],  W0,   HID, 0, 1.f);            // pw1
    set(1, in[4],  Wpd,  K2,  0, 1.f);            // pw2 -> Wpd[:, 0:2048]
    set(2, in[6],  W2,   HID, 0, 1.f);            // ow1
    set(3, in[8],  Wpd,  K2,  HID, -1.f);         // -ow2 -> Wpd[:, 2048:4096]
    set(4, in[10], W4,   HID, 0, 1.f);            // rw1
    set(5, in[12], W5,   HID, 0, 1.f);            // rw2
    set(6, in[14], Wqkv,            HID, 0, 1.f); // wq
    set(7, in[16], Wqkv + SZ_HH,    HID, 0, 1.f); // wk
    set(8, in[18], Wqkv + 2 * SZ_HH,HID, 0, 1.f); // wv
    set(9, in[20], W9,   HID, 0, 1.f);            // wo
    pack_bh10<<<dim3(HID / 32, HID / 64, 10), 256>>>(pb);

    // ---- launch 2: FFN weights, exact block count (8192 + 8192) ----
    PackBF pf; pf.s[0] = in[22]; pf.d[0] = Wf1; pf.s[1] = in[24]; pf.d[1] = Wf2;
    pack_bhffn<<<16384, 256>>>(pf);

    // ---- launch 3: inputs -> fp16, bias concat + bias diff ----
    PackMisc pm; pm.e = E; pm.o = Obs; pm.ep = Epk; pm.op = Opk;
    pm.b0 = in[15]; pm.b1 = in[17]; pm.b2 = in[19]; pm.bq = bqkv;
    pm.pb2 = in[5]; pm.ob2 = in[9]; pm.bd = bd;
    pack_misc<<<dim3(SZ_NH / 1024, 1, 3), 256>>>(pm);

    // 4: t0 = relu(E@pw1+pb1) -> TPw[:, 0:2048]  (ldc = 4096)
    G<1, true >(Epk, W0, in[3], nullptr, TPw, HID, HID, K2, 0);
    // 5: t1 = relu(Obs@ow1+ob1) -> TPw[:, 2048:4096]
    G<1, true >(Opk, W2, in[7], nullptr, TPw + HID, HID, HID, K2, 0);
    // 6: D = TPw @ [pw2; -ow2] + (pb2-ob2)  (K = 4096) -> Dp fp16
    G<0, true >(TPw, Wpd, bd, nullptr, Dp, HID, K2, HID, 0);
    // 7: t2 = relu(D@rw1+rb1)
    G<1, true >(Dp, W4, in[11], nullptr, TP, HID, HID, HID, 0);
    // 8: R = t2@rw2+rb2 (fp32)
    G<0, false>(TP, W5, in[13], nullptr, Rw, HID, HID, HID, 0);
    // 9: fused QKV projection (N = 6144)
    G<0, false>(Epk, Wqkv, bqkv, nullptr, QKV, QKVW, HID, QKVW, 0);
    attn_kernel<<<NTOK, 128>>>(QKV, Rw, TP);                  // att (fp16)
    // t3 = E + att@wo + bo (fp32)
    G<4, false>(TP, W9, in[21], E, Rw, HID, HID, HID, HID);
    ln_kernel<true><<<NTOK, 256>>>(Rw, in[26], in[27], X1, TP);
    // FFN
    G<2, true >(TP, Wf1, in[23], nullptr, F1, FFN, HID, FFN, 0);
    G<4, false>(F1, Wf2, in[25], X1, Rw, HID, FFN, HID, HID);
    ln_kernel<false><<<NTOK, 256>>>(Rw, in[28], in[29], out, nullptr);
}

// round 16
// speedup vs baseline: 1.1373x; 1.1373x over previous
#include <cuda_runtime.h>
#include <cuda_pipeline.h>
#include <cuda_fp16.h>
#include <mma.h>
#include <math.h>
#include <stdint.h>

using namespace nvcuda;

#define NTOK 8192
#define HID 2048
#define FFN 8192
#define NHEAD 16
#define DHEAD 128
#define QKVW (3 * HID)
#define K2 (2 * HID)
#define SZ_HH ((size_t)HID * HID)
#define SZ_NH ((size_t)NTOK * HID)
#define SZ_HF ((size_t)HID * FFN)
#define SZ_NF ((size_t)NTOK * FFN)

// ---------------- scratch (__device__ globals; no allocation) --------------
__device__ __half h_TPw[(size_t)NTOK * K2];                 // [t0 | t1] K-concat
__device__ __half h_Epk[SZ_NH], h_Opk[SZ_NH], h_TP[SZ_NH], h_Dp[SZ_NH], h_F1[SZ_NF];
__device__ __half h_w0[SZ_HH], h_w2[SZ_HH], h_w4[SZ_HH], h_w5[SZ_HH], h_w9[SZ_HH];
__device__ __half h_wqkv[3 * SZ_HH], h_wpd[(size_t)HID * K2];  // [pw2; -ow2] packed
__device__ __half h_wf1[SZ_HF], h_wf2[SZ_HF];
__device__ float g_Rw[SZ_NH], g_X1[SZ_NH], g_QKV[(size_t)NTOK * QKVW];
__device__ float g_bqkv[QKVW], g_bd[HID];

// ---------------- pack kernels (exactly 3 launches before first GEMM) ------
// W [Kd][Nd] fp32 (row stride Nd) -> out[(n)*ldk + koff + k] = scale * W[k][n]
__device__ __forceinline__ void pack_b_body(const float* __restrict__ W,
                                            __half* __restrict__ out, int Nd,
                                            int ldk, int koff, float scale,
                                            int kblk, int nblk) {
    __shared__ float s[32][65];
    const int k0 = kblk * 32, n0 = nblk * 64, t = threadIdx.x;
    #pragma unroll
    for (int i = 0; i < 8; i++) {
        int idx = t + i * 256, k = idx >> 6, n = idx & 63;
        s[k][n] = W[(size_t)(k0 + k) * Nd + n0 + n] * scale;
    }
    __syncthreads();
    #pragma unroll
    for (int i = 0; i < 2; i++) {
        int u = t + i * 256, n = u >> 3, kg = u & 7;
        __half2 h0 = __floats2half2_rn(s[kg * 4 + 0][n], s[kg * 4 + 1][n]);
        __half2 h1 = __floats2half2_rn(s[kg * 4 + 2][n], s[kg * 4 + 3][n]);
        *(uint2*)(out + (size_t)(n0 + n) * ldk + koff + k0 + kg * 4) =
            make_uint2(*(uint32_t*)&h0, *(uint32_t*)&h1);
    }
}
struct PackB10 { const float* s[10]; __half* d[10]; int ldk[10]; int koff[10]; float sc[10]; };
__global__ void pack_bh10(PackB10 p) {                 // launch 1: 10 HxH weights
    int z = blockIdx.z;
    pack_b_body(p.s[z], p.d[z], HID, p.ldk[z], p.koff[z], p.sc[z],
                blockIdx.x, blockIdx.y);
}
struct PackBF { const float* s[2]; __half* d[2]; };
__global__ void pack_bhffn(PackBF p) {                 // launch 2: fw1 + fw2, exact count
    int bid = blockIdx.x;
    if (bid < 8192) {        // fw1 [HID][FFN] -> [FFN][HID]: 64 kblk x 128 nblk
        pack_b_body(p.s[0], p.d[0], FFN, HID, 0, 1.0f, bid & 63, bid >> 6);
    } else {                 // fw2 [FFN][HID] -> [HID][FFN]: 256 kblk x 32 nblk
        int b = bid - 8192;
        pack_b_body(p.s[1], p.d[1], HID, FFN, 0, 1.0f, b & 255, b >> 8);
    }
}
struct PackMisc { const float* e; const float* o; __half* ep; __half* op;
                  const float* b0; const float* b1; const float* b2; float* bq;
                  const float* pb2; const float* ob2; float* bd; };
__global__ void pack_misc(PackMisc p) {                // launch 3: inputs fp16 + biases
    if (blockIdx.z < 2) {
        size_t u = ((size_t)blockIdx.x * 256 + threadIdx.x) * 4;
        const float* X = blockIdx.z ? p.o : p.e;
        __half* out = blockIdx.z ? p.op : p.ep;
        float4 v = *(const float4*)(X + u);
        __half2 h0 = __floats2half2_rn(v.x, v.y);
        __half2 h1 = __floats2half2_rn(v.z, v.w);
        *(uint2*)(out + u) = make_uint2(*(uint32_t*)&h0, *(uint32_t*)&h1);
    } else {
        int i = blockIdx.x * 256 + threadIdx.x;
        if (i < QKVW)
            p.bq[i] = (i < HID) ? p.b0[i] : (i < 2 * HID) ? p.b1[i - HID] : p.b2[i - 2 * HID];
        else if (i < QKVW + HID)
            p.bd[i - QKVW] = p.pb2[i - QKVW] - p.ob2[i - QKVW];
    }
}

// ---------------- fp16 wmma GEMM, 128x128 tile, BK=32, 3-stage cp.async ----
// A [M][Kd] fp16 row-major, Bm [Nd][Kd] fp16 (B^T), C = epi(A@B + bias)
// EPI: 0 bias, 1 relu, 2 leaky(0.01), 3 extra - x, 4 x + extra.  OPK: fp16 out.
#define BM 128
#define BN 128
#define BK 32
#define STG 3
#define ROWH 40
#define STAGE_H (BM * ROWH)
#define GEMM_SMEM (STG * STAGE_H * 2 * 2)

template<int EPI, bool OPK>
__global__ void __launch_bounds__(256, 2) gemm_h(
    const __half* __restrict__ A, const __half* __restrict__ Bm,
    const float* __restrict__ bias, const float* __restrict__ extra,
    void* __restrict__ Cv, int Kd, int ldc, int lde)
{
    extern __shared__ char smem[];
    __half* sA = (__half*)smem;
    __half* sB = sA + STG * STAGE_H;
    float*  sEp = (float*)smem;   // epilogue alias (after final sync)

    const int t = threadIdx.x, warp = t >> 5, lane = t & 31;
    const int bn = blockIdx.x, bm = blockIdx.y;
    const int wm = warp & 3, wn = warp >> 2;       // 4x2 warp grid, warp tile 32x64
    const int KT = Kd / BK;
    const __half* Ab = A + (size_t)bm * BM * Kd;
    const __half* Bb = Bm + (size_t)bn * BN * Kd;

    wmma::fragment<wmma::accumulator, 16, 16, 16, float> acc[2][4];
    #pragma unroll
    for (int i = 0; i < 2; i++)
        #pragma unroll
        for (int j = 0; j < 4; j++)
            wmma::fill_fragment(acc[i][j], 0.0f);

    auto load_tile = [&](int kt, int stg) {
        #pragma unroll
        for (int i = 0; i < 2; i++) {
            int c = t + i * 256, r = c >> 2, ch = c & 3;
            __pipeline_memcpy_async(sA + stg * STAGE_H + r * ROWH + ch * 8,
                                    Ab + (size_t)r * Kd + kt * BK + ch * 8, 16);
            __pipeline_memcpy_async(sB + stg * STAGE_H + r * ROWH + ch * 8,
                                    Bb + (size_t)r * Kd + kt * BK + ch * 8, 16);
        }
    };

    load_tile(0, 0); __pipeline_commit();
    load_tile(1, 1); __pipeline_commit();

    for (int kt = 0; kt < KT; ++kt) {
        __pipeline_wait_prior(1);
        __syncthreads();
        const int s = kt % STG;
        const __half* pA = sA + s * STAGE_H;
        const __half* pB = sB + s * STAGE_H;
        #pragma unroll
        for (int ks = 0; ks < 2; ++ks) {
            wmma::fragment<wmma::matrix_a, 16, 16, 16, __half, wmma::row_major> af[2];
            wmma::fragment<wmma::matrix_b, 16, 16, 16, __half, wmma::col_major> bf[4];
            #pragma unroll
            for (int fm = 0; fm < 2; ++fm)
                wmma::load_matrix_sync(af[fm], pA + (wm * 32 + fm * 16) * ROWH + ks * 16, ROWH);
            #pragma unroll
            for (int fn = 0; fn < 4; ++fn)
                wmma::load_matrix_sync(bf[fn], pB + (wn * 64 + fn * 16) * ROWH + ks * 16, ROWH);
            #pragma unroll
            for (int fm = 0; fm < 2; ++fm)
                #pragma unroll
                for (int fn = 0; fn < 4; ++fn)
                    wmma::mma_sync(acc[fm][fn], af[fm], bf[fn], acc[fm][fn]);
        }
        if (kt + 2 < KT) load_tile(kt + 2, (kt + 2) % STG);
        __pipeline_commit();
    }
    __syncthreads();

    // vectorized epilogue via per-warp smem scratch
    const size_t row0 = (size_t)bm * BM;
    const int    col0 = bn * BN;
    const int erow = lane >> 1, ecol = (lane & 1) * 8;
    #pragma unroll
    for (int fm = 0; fm < 2; ++fm) {
        #pragma unroll
        for (int fn = 0; fn < 4; ++fn) {
            wmma::store_matrix_sync(&sEp[warp * 256], acc[fm][fn], 16, wmma::mem_row_major);
            __syncwarp();
            const size_t gr = row0 + wm * 32 + fm * 16 + erow;
            const int    gc = col0 + wn * 64 + fn * 16 + ecol;
            float4 v0 = *(float4*)&sEp[warp * 256 + erow * 16 + ecol];
            float4 v1 = *(float4*)&sEp[warp * 256 + erow * 16 + ecol + 4];
            float4 b0 = *(const float4*)(bias + gc);
            float4 b1 = *(const float4*)(bias + gc + 4);
            float x[8] = { v0.x + b0.x, v0.y + b0.y, v0.z + b0.z, v0.w + b0.w,
                           v1.x + b1.x, v1.y + b1.y, v1.z + b1.z, v1.w + b1.w };
            if (EPI == 1) {
                #pragma unroll
                for (int q = 0; q < 8; q++) x[q] = fmaxf(x[q], 0.0f);
            } else if (EPI == 2) {
                #pragma unroll
                for (int q = 0; q < 8; q++) x[q] = (x[q] >= 0.f) ? x[q] : 0.01f * x[q];
            } else if (EPI == 3 || EPI == 4) {
                float4 e0 = *(const float4*)(extra + gr * (size_t)lde + gc);
                float4 e1 = *(const float4*)(extra + gr * (size_t)lde + gc + 4);
                float ev[8] = { e0.x, e0.y, e0.z, e0.w, e1.x, e1.y, e1.z, e1.w };
                #pragma unroll
                for (int q = 0; q < 8; q++)
                    x[q] = (EPI == 3) ? (ev[q] - x[q]) : (x[q] + ev[q]);
            }
            if (OPK) {
                __half2 p0 = __floats2half2_rn(x[0], x[1]), p1 = __floats2half2_rn(x[2], x[3]);
                __half2 p2 = __floats2half2_rn(x[4], x[5]), p3 = __floats2half2_rn(x[6], x[7]);
                *(uint4*)((__half*)Cv + gr * (size_t)ldc + gc) =
                    make_uint4(*(uint32_t*)&p0, *(uint32_t*)&p1, *(uint32_t*)&p2, *(uint32_t*)&p3);
            } else {
                float* cp = (float*)Cv + gr * (size_t)ldc + gc;
                *(float4*)cp       = make_float4(x[0], x[1], x[2], x[3]);
                *(float4*)(cp + 4) = make_float4(x[4], x[5], x[6], x[7]);
            }
            __syncwarp();
        }
    }
}

// ---------------- per-token head-vs-head attention (exact fp32) ------------
// QKV fused buffer: row stride 6144, Q at +0, K at +2048, V at +4096
__global__ void __launch_bounds__(128) attn_kernel(
    const float* __restrict__ QKV, const float* __restrict__ R,
    __half* __restrict__ outp)
{
    __shared__ __align__(16) float sQ[NHEAD][DHEAD], sK[NHEAD][DHEAD],
                                   sV[NHEAD][DHEAD], sR[NHEAD][DHEAD];
    const int n = blockIdx.x, t = threadIdx.x;
    const size_t b6 = (size_t)n * QKVW, base = (size_t)n * HID;
    #pragma unroll
    for (int i = t; i < HID / 4; i += 128) {
        ((float4*)sQ)[i] = ((const float4*)(QKV + b6))[i];
        ((float4*)sK)[i] = ((const float4*)(QKV + b6 + HID))[i];
        ((float4*)sV)[i] = ((const float4*)(QKV + b6 + 2 * HID))[i];
        ((float4*)sR)[i] = ((const float4*)(R + base))[i];
    }
    __syncthreads();
    const int warp = t >> 5, lane = t & 31;
    const float scale = 0.08838834764831845f;
    #pragma unroll
    for (int hh = 0; hh < 4; ++hh) {
        const int h = warp * 4 + hh;
        const float q0 = sQ[h][lane], q1 = sQ[h][lane + 32],
                    q2 = sQ[h][lane + 64], q3 = sQ[h][lane + 96];
        float sc[NHEAD];
        #pragma unroll
        for (int g = 0; g < NHEAD; ++g) {
            float s1 = q0 * sK[g][lane] + q1 * sK[g][lane + 32]
                     + q2 * sK[g][lane + 64] + q3 * sK[g][lane + 96];
            float s2 = q0 * sR[g][lane] + q1 * sR[g][lane + 32]
                     + q2 * sR[g][lane + 64] + q3 * sR[g][lane + 96];
            float v = s1 * scale - s2;
            #pragma unroll
            for (int o = 16; o > 0; o >>= 1) v += __shfl_xor_sync(0xffffffffu, v, o);
            sc[g] = v;
        }
        float m = sc[0];
        #pragma unroll
        for (int g = 1; g < NHEAD; ++g) m = fmaxf(m, sc[g]);
        float den = 0.f;
        #pragma unroll
        for (int g = 0; g < NHEAD; ++g) { sc[g] = expf(sc[g] - m); den += sc[g]; }
        const float inv = 1.0f / den;
        float o0 = 0, o1 = 0, o2 = 0, o3 = 0;
        #pragma unroll
        for (int g = 0; g < NHEAD; ++g) {
            float p = sc[g] * inv;
            o0 += p * sV[g][lane];      o1 += p * sV[g][lane + 32];
            o2 += p * sV[g][lane + 64]; o3 += p * sV[g][lane + 96];
        }
        __half* op = outp + base + (size_t)h * DHEAD;
        op[lane]      = __float2half_rn(o0);
        op[lane + 32] = __float2half_rn(o1);
        op[lane + 64] = __float2half_rn(o2);
        op[lane + 96] = __float2half_rn(o3);
    }
}

// ---------------- layernorm; optional fp16 copy ----------------------------
template<bool PK2>
__global__ void __launch_bounds__(256) ln_kernel(
    const float* __restrict__ x, const float* __restrict__ gamma,
    const float* __restrict__ beta, float* __restrict__ outr,
    __half* __restrict__ outp)
{
    __shared__ float sh[8];
    const int row = blockIdx.x, t = threadIdx.x, lane = t & 31, w = t >> 5;
    const float4* xr = (const float4*)(x + (size_t)row * HID);
    float4 a = xr[t], b = xr[t + 256];
    float s = a.x + a.y + a.z + a.w + b.x + b.y + b.z + b.w;
    #pragma unroll
    for (int o = 16; o > 0; o >>= 1) s += __shfl_xor_sync(0xffffffffu, s, o);
    if (lane == 0) sh[w] = s;
    __syncthreads();
    float tot = 0;
    #pragma unroll
    for (int i = 0; i < 8; i++) tot += sh[i];
    const float mean = tot * (1.0f / HID);
    float d, sq = 0;
    d = a.x - mean; sq += d * d; d = a.y - mean; sq += d * d;
    d = a.z - mean; sq += d * d; d = a.w - mean; sq += d * d;
    d = b.x - mean; sq += d * d; d = b.y - mean; sq += d * d;
    d = b.z - mean; sq += d * d; d = b.w - mean; sq += d * d;
    __syncthreads();
    #pragma unroll
    for (int o = 16; o > 0; o >>= 1) sq += __shfl_xor_sync(0xffffffffu, sq, o);
    if (lane == 0) sh[w] = sq;
    __syncthreads();
    tot = 0;
    #pragma unroll
    for (int i = 0; i < 8; i++) tot += sh[i];
    const float rstd = rsqrtf(tot * (1.0f / HID) + 1e-5f);
    float4 g0 = ((const float4*)gamma)[t], gA = ((const float4*)gamma)[t + 256];
    float4 e0 = ((const float4*)beta)[t],  eA = ((const float4*)beta)[t + 256];
    float4 r0 = make_float4((a.x - mean) * rstd * g0.x + e0.x, (a.y - mean) * rstd * g0.y + e0.y,
                            (a.z - mean) * rstd * g0.z + e0.z, (a.w - mean) * rstd * g0.w + e0.w);
    float4 r1 = make_float4((b.x - mean) * rstd * gA.x + eA.x, (b.y - mean) * rstd * gA.y + eA.y,
                            (b.z - mean) * rstd * gA.z + eA.z, (b.w - mean) * rstd * gA.w + eA.w);
    float4* o4 = (float4*)(outr + (size_t)row * HID);
    o4[t] = r0; o4[t + 256] = r1;
    if (PK2) {
        __half2 p0 = __floats2half2_rn(r0.x, r0.y), p1 = __floats2half2_rn(r0.z, r0.w);
        __half2 p2 = __floats2half2_rn(r1.x, r1.y), p3 = __floats2half2_rn(r1.z, r1.w);
        __half* op = outp + (size_t)row * HID;
        *(uint2*)(op + t * 4)        = make_uint2(*(uint32_t*)&p0, *(uint32_t*)&p1);
        *(uint2*)(op + t * 4 + 1024) = make_uint2(*(uint32_t*)&p2, *(uint32_t*)&p3);
    }
}

// ---------------- host ------------------------------------------------------
template<int EPI, bool OPK>
static void G(const __half* A, const __half* B, const float* bias, const float* extra,
              void* C, int Nd, int Kd, int ldc, int lde)
{
    cudaFuncSetAttribute(gemm_h<EPI, OPK>, cudaFuncAttributeMaxDynamicSharedMemorySize, GEMM_SMEM);
    gemm_h<EPI, OPK><<<dim3(Nd / BN, NTOK / BM), 256, GEMM_SMEM>>>(
        A, B, bias, extra, C, Kd, ldc, lde);
}

extern "C" void kernel_launch(void* const* d_in, const int* in_sizes, int n_in,
                              void* d_out, int out_size)
{
    const float* in[30];
    for (int i = 0; i < 30; i++) in[i] = (const float*)d_in[i];
    const float *E = in[0], *Obs = in[1];
    float* out = (float*)d_out;

    __half *TPw, *Epk, *Opk, *TP, *Dp, *F1;
    __half *W0, *W2, *W4, *W5, *W9, *Wqkv, *Wpd, *Wf1, *Wf2;
    float *Rw, *X1, *QKV, *bqkv, *bd;
    cudaGetSymbolAddress((void**)&TPw, h_TPw);
    cudaGetSymbolAddress((void**)&Epk, h_Epk); cudaGetSymbolAddress((void**)&Opk, h_Opk);
    cudaGetSymbolAddress((void**)&TP,  h_TP);  cudaGetSymbolAddress((void**)&Dp,  h_Dp);
    cudaGetSymbolAddress((void**)&F1,  h_F1);
    cudaGetSymbolAddress((void**)&W0, h_w0);   cudaGetSymbolAddress((void**)&W2, h_w2);
    cudaGetSymbolAddress((void**)&W4, h_w4);   cudaGetSymbolAddress((void**)&W5, h_w5);
    cudaGetSymbolAddress((void**)&W9, h_w9);   cudaGetSymbolAddress((void**)&Wqkv, h_wqkv);
    cudaGetSymbolAddress((void**)&Wpd, h_wpd);
    cudaGetSymbolAddress((void**)&Wf1, h_wf1); cudaGetSymbolAddress((void**)&Wf2, h_wf2);
    cudaGetSymbolAddress((void**)&Rw, g_Rw);   cudaGetSymbolAddress((void**)&X1, g_X1);
    cudaGetSymbolAddress((void**)&QKV, g_QKV); cudaGetSymbolAddress((void**)&bqkv, g_bqkv);
    cudaGetSymbolAddress((void**)&bd, g_bd);

    // ---- launch 1: 10 HxH weight packs (pw2/ow2 go K-concatenated into Wpd) ----
    PackB10 pb;
    auto set = [&](int i, const float* s, __half* d, int ldk, int koff, float sc) {
        pb.s[i] = s; pb.d[i] = d; pb.ldk[i] = ldk; pb.koff[i] = koff; pb.sc[i] = sc;
    };
    set(0, in[2],  W0,   HID, 0, 1.f);            // pw1
    set(1, in[4],  Wpd,  K2,  0, 1.f);            // pw2 -> Wpd[:, 0:2048]
    set(2, in[6],  W2,   HID, 0, 1.f);            // ow1
    set(3, in[8],  Wpd,  K2,  HID, -1.f);         // -ow2 -> Wpd[:, 2048:4096]
    set(4, in[10], W4,   HID, 0, 1.f);            // rw1
    set(5, in[12], W5,   HID, 0, 1.f);            // rw2
    set(6, in[14], Wqkv,            HID, 0, 1.f); // wq
    set(7, in[16], Wqkv + SZ_HH,    HID, 0, 1.f); // wk
    set(8, in[18], Wqkv + 2 * SZ_HH,HID, 0, 1.f); // wv
    set(9, in[20], W9,   HID, 0, 1.f);            // wo
    pack_bh10<<<dim3(HID / 32, HID / 64, 10), 256>>>(pb);

    // ---- launch 2: FFN weights, exact block count (8192 + 8192) ----
    PackBF pf; pf.s[0] = in[22]; pf.d[0] = Wf1; pf.s[1] = in[24]; pf.d[1] = Wf2;
    pack_bhffn<<<16384, 256>>>(pf);

    // ---- launch 3: inputs -> fp16, bias concat + bias diff ----
    PackMisc pm; pm.e = E; pm.o = Obs; pm.ep = Epk; pm.op = Opk;
    pm.b0 = in[15]; pm.b1 = in[17]; pm.b2 = in[19]; pm.bq = bqkv;
    pm.pb2 = in[5]; pm.ob2 = in[9]; pm.bd = bd;
    pack_misc<<<dim3(SZ_NH / 1024, 1, 3), 256>>>(pm);

    // 4: t0 = relu(E@pw1+pb1) -> TPw[:, 0:2048]  (ldc = 4096)
    G<1, true >(Epk, W0, in[3], nullptr, TPw, HID, HID, K2, 0);
    // 5: t1 = relu(Obs@ow1+ob1) -> TPw[:, 2048:4096]
    G<1, true >(Opk, W2, in[7], nullptr, TPw + HID, HID, HID, K2, 0);
    // 6: D = TPw @ [pw2; -ow2] + (pb2-ob2)  (K = 4096) -> Dp fp16
    G<0, true >(TPw, Wpd, bd, nullptr, Dp, HID, K2, HID, 0);
    // 7: t2 = relu(D@rw1+rb1)
    G<1, true >(Dp, W4, in[11], nullptr, TP, HID, HID, HID, 0);
    // 8: R = t2@rw2+rb2 (fp32)
    G<0, false>(TP, W5, in[13], nullptr, Rw, HID, HID, HID, 0);
    // 9: fused QKV projection (N = 6144)
    G<0, false>(Epk, Wqkv, bqkv, nullptr, QKV, QKVW, HID, QKVW, 0);
    attn_kernel<<<NTOK, 128>>>(QKV, Rw, TP);                  // att (fp16)
    // t3 = E + att@wo + bo (fp32)
    G<4, false>(TP, W9, in[21], E, Rw, HID, HID, HID, HID);
    ln_kernel<true><<<NTOK, 256>>>(Rw, in[26], in[27], X1, TP);
    // FFN
    G<2, true >(TP, Wf1, in[23], nullptr, F1, FFN, HID, FFN, 0);
    G<4, false>(F1, Wf2, in[25], X1, Rw, HID, FFN, HID, HID);
    ln_kernel<false><<<NTOK, 256>>>(Rw, in[28], in[29], out, nullptr);
}

// round 17
// speedup vs baseline: 1.1421x; 1.0042x over previous
#include <cuda_runtime.h>
#include <cuda_pipeline.h>
#include <cuda_fp16.h>
#include <mma.h>
#include <math.h>
#include <stdint.h>

using namespace nvcuda;

#define NTOK 8192
#define HID 2048
#define FFN 8192
#define NHEAD 16
#define DHEAD 128
#define QKVW (3 * HID)
#define K2 (2 * HID)
#define SZ_HH ((size_t)HID * HID)
#define SZ_NH ((size_t)NTOK * HID)
#define SZ_HF ((size_t)HID * FFN)
#define SZ_NF ((size_t)NTOK * FFN)

// ---------------- scratch (__device__ globals; no allocation) --------------
__device__ __half h_TPw[(size_t)NTOK * K2];                 // [t0 | t1] K-concat
__device__ __half h_Epk[SZ_NH], h_Opk[SZ_NH], h_TP[SZ_NH], h_Dp[SZ_NH], h_F1[SZ_NF];
__device__ __half h_QKV[(size_t)NTOK * QKVW];               // fp16 QKV (was fp32)
__device__ __half h_w0[SZ_HH], h_w2[SZ_HH], h_w4[SZ_HH], h_w5[SZ_HH], h_w9[SZ_HH];
__device__ __half h_wqkv[3 * SZ_HH], h_wpd[(size_t)HID * K2];  // [pw2; -ow2] packed
__device__ __half h_wf1[SZ_HF], h_wf2[SZ_HF];
__device__ float g_Rw[SZ_NH], g_X1[SZ_NH];
__device__ float g_bqkv[QKVW], g_bd[HID];

// ---------------- pack kernels (exactly 3 launches before first GEMM) ------
// W [Kd][Nd] fp32 (row stride Nd) -> out[(n)*ldk + koff + k] = scale * W[k][n]
__device__ __forceinline__ void pack_b_body(const float* __restrict__ W,
                                            __half* __restrict__ out, int Nd,
                                            int ldk, int koff, float scale,
                                            int kblk, int nblk) {
    __shared__ float s[32][65];
    const int k0 = kblk * 32, n0 = nblk * 64, t = threadIdx.x;
    #pragma unroll
    for (int i = 0; i < 8; i++) {
        int idx = t + i * 256, k = idx >> 6, n = idx & 63;
        s[k][n] = W[(size_t)(k0 + k) * Nd + n0 + n] * scale;
    }
    __syncthreads();
    #pragma unroll
    for (int i = 0; i < 2; i++) {
        int u = t + i * 256, n = u >> 3, kg = u & 7;
        __half2 h0 = __floats2half2_rn(s[kg * 4 + 0][n], s[kg * 4 + 1][n]);
        __half2 h1 = __floats2half2_rn(s[kg * 4 + 2][n], s[kg * 4 + 3][n]);
        *(uint2*)(out + (size_t)(n0 + n) * ldk + koff + k0 + kg * 4) =
            make_uint2(*(uint32_t*)&h0, *(uint32_t*)&h1);
    }
}
struct PackB10 { const float* s[10]; __half* d[10]; int ldk[10]; int koff[10]; float sc[10]; };
__global__ void pack_bh10(PackB10 p) {                 // launch 1: 10 HxH weights
    int z = blockIdx.z;
    pack_b_body(p.s[z], p.d[z], HID, p.ldk[z], p.koff[z], p.sc[z],
                blockIdx.x, blockIdx.y);
}
struct PackBF { const float* s[2]; __half* d[2]; };
__global__ void pack_bhffn(PackBF p) {                 // launch 2: fw1 + fw2, exact count
    int bid = blockIdx.x;
    if (bid < 8192) {        // fw1 [HID][FFN] -> [FFN][HID]: 64 kblk x 128 nblk
        pack_b_body(p.s[0], p.d[0], FFN, HID, 0, 1.0f, bid & 63, bid >> 6);
    } else {                 // fw2 [FFN][HID] -> [HID][FFN]: 256 kblk x 32 nblk
        int b = bid - 8192;
        pack_b_body(p.s[1], p.d[1], HID, FFN, 0, 1.0f, b & 255, b >> 8);
    }
}
struct PackMisc { const float* e; const float* o; __half* ep; __half* op;
                  const float* b0; const float* b1; const float* b2; float* bq;
                  const float* pb2; const float* ob2; float* bd; };
__global__ void pack_misc(PackMisc p) {                // launch 3: inputs fp16 + biases
    if (blockIdx.z < 2) {
        size_t u = ((size_t)blockIdx.x * 256 + threadIdx.x) * 4;
        const float* X = blockIdx.z ? p.o : p.e;
        __half* out = blockIdx.z ? p.op : p.ep;
        float4 v = *(const float4*)(X + u);
        __half2 h0 = __floats2half2_rn(v.x, v.y);
        __half2 h1 = __floats2half2_rn(v.z, v.w);
        *(uint2*)(out + u) = make_uint2(*(uint32_t*)&h0, *(uint32_t*)&h1);
    } else {
        int i = blockIdx.x * 256 + threadIdx.x;
        if (i < QKVW)
            p.bq[i] = (i < HID) ? p.b0[i] : (i < 2 * HID) ? p.b1[i - HID] : p.b2[i - 2 * HID];
        else if (i < QKVW + HID)
            p.bd[i - QKVW] = p.pb2[i - QKVW] - p.ob2[i - QKVW];
    }
}

// ---------------- fp16 wmma GEMM, 128x128 tile, BK=32, 3-stage cp.async ----
// A [M][Kd] fp16 row-major, Bm [Nd][Kd] fp16 (B^T), C = epi(A@B + bias)
// EPI: 0 bias, 1 relu, 2 leaky(0.01), 3 extra - x, 4 x + extra.  OPK: fp16 out.
#define BM 128
#define BN 128
#define BK 32
#define STG 3
#define ROWH 40
#define STAGE_H (BM * ROWH)
#define GEMM_SMEM (STG * STAGE_H * 2 * 2)

template<int EPI, bool OPK>
__global__ void __launch_bounds__(256, 2) gemm_h(
    const __half* __restrict__ A, const __half* __restrict__ Bm,
    const float* __restrict__ bias, const float* __restrict__ extra,
    void* __restrict__ Cv, int Kd, int ldc, int lde)
{
    extern __shared__ char smem[];
    __half* sA = (__half*)smem;
    __half* sB = sA + STG * STAGE_H;
    float*  sEp = (float*)smem;   // epilogue alias (after final sync)

    const int t = threadIdx.x, warp = t >> 5, lane = t & 31;
    const int bn = blockIdx.x, bm = blockIdx.y;
    const int wm = warp & 3, wn = warp >> 2;       // 4x2 warp grid, warp tile 32x64
    const int KT = Kd / BK;
    const __half* Ab = A + (size_t)bm * BM * Kd;
    const __half* Bb = Bm + (size_t)bn * BN * Kd;

    wmma::fragment<wmma::accumulator, 16, 16, 16, float> acc[2][4];
    #pragma unroll
    for (int i = 0; i < 2; i++)
        #pragma unroll
        for (int j = 0; j < 4; j++)
            wmma::fill_fragment(acc[i][j], 0.0f);

    auto load_tile = [&](int kt, int stg) {
        #pragma unroll
        for (int i = 0; i < 2; i++) {
            int c = t + i * 256, r = c >> 2, ch = c & 3;
            __pipeline_memcpy_async(sA + stg * STAGE_H + r * ROWH + ch * 8,
                                    Ab + (size_t)r * Kd + kt * BK + ch * 8, 16);
            __pipeline_memcpy_async(sB + stg * STAGE_H + r * ROWH + ch * 8,
                                    Bb + (size_t)r * Kd + kt * BK + ch * 8, 16);
        }
    };

    load_tile(0, 0); __pipeline_commit();
    load_tile(1, 1); __pipeline_commit();

    for (int kt = 0; kt < KT; ++kt) {
        __pipeline_wait_prior(1);
        __syncthreads();
        const int s = kt % STG;
        const __half* pA = sA + s * STAGE_H;
        const __half* pB = sB + s * STAGE_H;
        #pragma unroll
        for (int ks = 0; ks < 2; ++ks) {
            wmma::fragment<wmma::matrix_a, 16, 16, 16, __half, wmma::row_major> af[2];
            wmma::fragment<wmma::matrix_b, 16, 16, 16, __half, wmma::col_major> bf[4];
            #pragma unroll
            for (int fm = 0; fm < 2; ++fm)
                wmma::load_matrix_sync(af[fm], pA + (wm * 32 + fm * 16) * ROWH + ks * 16, ROWH);
            #pragma unroll
            for (int fn = 0; fn < 4; ++fn)
                wmma::load_matrix_sync(bf[fn], pB + (wn * 64 + fn * 16) * ROWH + ks * 16, ROWH);
            #pragma unroll
            for (int fm = 0; fm < 2; ++fm)
                #pragma unroll
                for (int fn = 0; fn < 4; ++fn)
                    wmma::mma_sync(acc[fm][fn], af[fm], bf[fn], acc[fm][fn]);
        }
        if (kt + 2 < KT) load_tile(kt + 2, (kt + 2) % STG);
        __pipeline_commit();
    }
    __syncthreads();

    // vectorized epilogue via per-warp smem scratch
    const size_t row0 = (size_t)bm * BM;
    const int    col0 = bn * BN;
    const int erow = lane >> 1, ecol = (lane & 1) * 8;
    #pragma unroll
    for (int fm = 0; fm < 2; ++fm) {
        #pragma unroll
        for (int fn = 0; fn < 4; ++fn) {
            wmma::store_matrix_sync(&sEp[warp * 256], acc[fm][fn], 16, wmma::mem_row_major);
            __syncwarp();
            const size_t gr = row0 + wm * 32 + fm * 16 + erow;
            const int    gc = col0 + wn * 64 + fn * 16 + ecol;
            float4 v0 = *(float4*)&sEp[warp * 256 + erow * 16 + ecol];
            float4 v1 = *(float4*)&sEp[warp * 256 + erow * 16 + ecol + 4];
            float4 b0 = *(const float4*)(bias + gc);
            float4 b1 = *(const float4*)(bias + gc + 4);
            float x[8] = { v0.x + b0.x, v0.y + b0.y, v0.z + b0.z, v0.w + b0.w,
                           v1.x + b1.x, v1.y + b1.y, v1.z + b1.z, v1.w + b1.w };
            if (EPI == 1) {
                #pragma unroll
                for (int q = 0; q < 8; q++) x[q] = fmaxf(x[q], 0.0f);
            } else if (EPI == 2) {
                #pragma unroll
                for (int q = 0; q < 8; q++) x[q] = (x[q] >= 0.f) ? x[q] : 0.01f * x[q];
            } else if (EPI == 3 || EPI == 4) {
                float4 e0 = *(const float4*)(extra + gr * (size_t)lde + gc);
                float4 e1 = *(const float4*)(extra + gr * (size_t)lde + gc + 4);
                float ev[8] = { e0.x, e0.y, e0.z, e0.w, e1.x, e1.y, e1.z, e1.w };
                #pragma unroll
                for (int q = 0; q < 8; q++)
                    x[q] = (EPI == 3) ? (ev[q] - x[q]) : (x[q] + ev[q]);
            }
            if (OPK) {
                __half2 p0 = __floats2half2_rn(x[0], x[1]), p1 = __floats2half2_rn(x[2], x[3]);
                __half2 p2 = __floats2half2_rn(x[4], x[5]), p3 = __floats2half2_rn(x[6], x[7]);
                *(uint4*)((__half*)Cv + gr * (size_t)ldc + gc) =
                    make_uint4(*(uint32_t*)&p0, *(uint32_t*)&p1, *(uint32_t*)&p2, *(uint32_t*)&p3);
            } else {
                float* cp = (float*)Cv + gr * (size_t)ldc + gc;
                *(float4*)cp       = make_float4(x[0], x[1], x[2], x[3]);
                *(float4*)(cp + 4) = make_float4(x[4], x[5], x[6], x[7]);
            }
            __syncwarp();
        }
    }
}

// ---------------- per-token head-vs-head attention (fp32 compute) ----------
// QKV fused fp16 buffer: row stride 6144, Q at +0, K at +2048, V at +4096
// R fp16.  All math in fp32 after converting on the smem fill.
__global__ void __launch_bounds__(128) attn_kernel(
    const __half* __restrict__ QKV6, const __half* __restrict__ R,
    __half* __restrict__ outp)
{
    __shared__ __align__(16) float sQ[NHEAD][DHEAD], sK[NHEAD][DHEAD],
                                   sV[NHEAD][DHEAD], sR[NHEAD][DHEAD];
    const int n = blockIdx.x, t = threadIdx.x;
    const size_t b6 = (size_t)n * QKVW, base = (size_t)n * HID;
    const uint2* q2 = (const uint2*)(QKV6 + b6);
    const uint2* k2 = (const uint2*)(QKV6 + b6 + HID);
    const uint2* v2 = (const uint2*)(QKV6 + b6 + 2 * HID);
    const uint2* r2 = (const uint2*)(R + base);
    #pragma unroll
    for (int i = t; i < HID / 4; i += 128) {
        uint2 qa = q2[i], ka = k2[i], va = v2[i], ra = r2[i];
        float2 f0, f1;
        f0 = __half22float2(*(__half2*)&qa.x); f1 = __half22float2(*(__half2*)&qa.y);
        ((float4*)sQ)[i] = make_float4(f0.x, f0.y, f1.x, f1.y);
        f0 = __half22float2(*(__half2*)&ka.x); f1 = __half22float2(*(__half2*)&ka.y);
        ((float4*)sK)[i] = make_float4(f0.x, f0.y, f1.x, f1.y);
        f0 = __half22float2(*(__half2*)&va.x); f1 = __half22float2(*(__half2*)&va.y);
        ((float4*)sV)[i] = make_float4(f0.x, f0.y, f1.x, f1.y);
        f0 = __half22float2(*(__half2*)&ra.x); f1 = __half22float2(*(__half2*)&ra.y);
        ((float4*)sR)[i] = make_float4(f0.x, f0.y, f1.x, f1.y);
    }
    __syncthreads();
    const int warp = t >> 5, lane = t & 31;
    const float scale = 0.08838834764831845f;
    #pragma unroll
    for (int hh = 0; hh < 4; ++hh) {
        const int h = warp * 4 + hh;
        const float q0 = sQ[h][lane], q1 = sQ[h][lane + 32],
                    q2v = sQ[h][lane + 64], q3 = sQ[h][lane + 96];
        float sc[NHEAD];
        #pragma unroll
        for (int g = 0; g < NHEAD; ++g) {
            float s1 = q0 * sK[g][lane] + q1 * sK[g][lane + 32]
                     + q2v * sK[g][lane + 64] + q3 * sK[g][lane + 96];
            float s2 = q0 * sR[g][lane] + q1 * sR[g][lane + 32]
                     + q2v * sR[g][lane + 64] + q3 * sR[g][lane + 96];
            float v = s1 * scale - s2;
            #pragma unroll
            for (int o = 16; o > 0; o >>= 1) v += __shfl_xor_sync(0xffffffffu, v, o);
            sc[g] = v;
        }
        float m = sc[0];
        #pragma unroll
        for (int g = 1; g < NHEAD; ++g) m = fmaxf(m, sc[g]);
        float den = 0.f;
        #pragma unroll
        for (int g = 0; g < NHEAD; ++g) { sc[g] = expf(sc[g] - m); den += sc[g]; }
        const float inv = 1.0f / den;
        float o0 = 0, o1 = 0, o2 = 0, o3 = 0;
        #pragma unroll
        for (int g = 0; g < NHEAD; ++g) {
            float p = sc[g] * inv;
            o0 += p * sV[g][lane];      o1 += p * sV[g][lane + 32];
            o2 += p * sV[g][lane + 64]; o3 += p * sV[g][lane + 96];
        }
        __half* op = outp + base + (size_t)h * DHEAD;
        op[lane]      = __float2half_rn(o0);
        op[lane + 32] = __float2half_rn(o1);
        op[lane + 64] = __float2half_rn(o2);
        op[lane + 96] = __float2half_rn(o3);
    }
}

// ---------------- layernorm; optional fp16 copy ----------------------------
template<bool PK2>
__global__ void __launch_bounds__(256) ln_kernel(
    const float* __restrict__ x, const float* __restrict__ gamma,
    const float* __restrict__ beta, float* __restrict__ outr,
    __half* __restrict__ outp)
{
    __shared__ float sh[8];
    const int row = blockIdx.x, t = threadIdx.x, lane = t & 31, w = t >> 5;
    const float4* xr = (const float4*)(x + (size_t)row * HID);
    float4 a = xr[t], b = xr[t + 256];
    float s = a.x + a.y + a.z + a.w + b.x + b.y + b.z + b.w;
    #pragma unroll
    for (int o = 16; o > 0; o >>= 1) s += __shfl_xor_sync(0xffffffffu, s, o);
    if (lane == 0) sh[w] = s;
    __syncthreads();
    float tot = 0;
    #pragma unroll
    for (int i = 0; i < 8; i++) tot += sh[i];
    const float mean = tot * (1.0f / HID);
    float d, sq = 0;
    d = a.x - mean; sq += d * d; d = a.y - mean; sq += d * d;
    d = a.z - mean; sq += d * d; d = a.w - mean; sq += d * d;
    d = b.x - mean; sq += d * d; d = b.y - mean; sq += d * d;
    d = b.z - mean; sq += d * d; d = b.w - mean; sq += d * d;
    __syncthreads();
    #pragma unroll
    for (int o = 16; o > 0; o >>= 1) sq += __shfl_xor_sync(0xffffffffu, sq, o);
    if (lane == 0) sh[w] = sq;
    __syncthreads();
    tot = 0;
    #pragma unroll
    for (int i = 0; i < 8; i++) tot += sh[i];
    const float rstd = rsqrtf(tot * (1.0f / HID) + 1e-5f);
    float4 g0 = ((const float4*)gamma)[t], gA = ((const float4*)gamma)[t + 256];
    float4 e0 = ((const float4*)beta)[t],  eA = ((const float4*)beta)[t + 256];
    float4 r0 = make_float4((a.x - mean) * rstd * g0.x + e0.x, (a.y - mean) * rstd * g0.y + e0.y,
                            (a.z - mean) * rstd * g0.z + e0.z, (a.w - mean) * rstd * g0.w + e0.w);
    float4 r1 = make_float4((b.x - mean) * rstd * gA.x + eA.x, (b.y - mean) * rstd * gA.y + eA.y,
                            (b.z - mean) * rstd * gA.z + eA.z, (b.w - mean) * rstd * gA.w + eA.w);
    float4* o4 = (float4*)(outr + (size_t)row * HID);
    o4[t] = r0; o4[t + 256] = r1;
    if (PK2) {
        __half2 p0 = __floats2half2_rn(r0.x, r0.y), p1 = __floats2half2_rn(r0.z, r0.w);
        __half2 p2 = __floats2half2_rn(r1.x, r1.y), p3 = __floats2half2_rn(r1.z, r1.w);
        __half* op = outp + (size_t)row * HID;
        *(uint2*)(op + t * 4)        = make_uint2(*(uint32_t*)&p0, *(uint32_t*)&p1);
        *(uint2*)(op + t * 4 + 1024) = make_uint2(*(uint32_t*)&p2, *(uint32_t*)&p3);
    }
}

// ---------------- host ------------------------------------------------------
template<int EPI, bool OPK>
static void G(const __half* A, const __half* B, const float* bias, const float* extra,
              void* C, int Nd, int Kd, int ldc, int lde)
{
    cudaFuncSetAttribute(gemm_h<EPI, OPK>, cudaFuncAttributeMaxDynamicSharedMemorySize, GEMM_SMEM);
    gemm_h<EPI, OPK><<<dim3(Nd / BN, NTOK / BM), 256, GEMM_SMEM>>>(
        A, B, bias, extra, C, Kd, ldc, lde);
}

extern "C" void kernel_launch(void* const* d_in, const int* in_sizes, int n_in,
                              void* d_out, int out_size)
{
    const float* in[30];
    for (int i = 0; i < 30; i++) in[i] = (const float*)d_in[i];
    const float *E = in[0], *Obs = in[1];
    float* out = (float*)d_out;

    __half *TPw, *Epk, *Opk, *TP, *Dp, *F1, *QKVh;
    __half *W0, *W2, *W4, *W5, *W9, *Wqkv, *Wpd, *Wf1, *Wf2;
    float *Rw, *X1, *bqkv, *bd;
    cudaGetSymbolAddress((void**)&TPw, h_TPw);
    cudaGetSymbolAddress((void**)&Epk, h_Epk); cudaGetSymbolAddress((void**)&Opk, h_Opk);
    cudaGetSymbolAddress((void**)&TP,  h_TP);  cudaGetSymbolAddress((void**)&Dp,  h_Dp);
    cudaGetSymbolAddress((void**)&F1,  h_F1);  cudaGetSymbolAddress((void**)&QKVh, h_QKV);
    cudaGetSymbolAddress((void**)&W0, h_w0);   cudaGetSymbolAddress((void**)&W2, h_w2);
    cudaGetSymbolAddress((void**)&W4, h_w4);   cudaGetSymbolAddress((void**)&W5, h_w5);
    cudaGetSymbolAddress((void**)&W9, h_w9);   cudaGetSymbolAddress((void**)&Wqkv, h_wqkv);
    cudaGetSymbolAddress((void**)&Wpd, h_wpd);
    cudaGetSymbolAddress((void**)&Wf1, h_wf1); cudaGetSymbolAddress((void**)&Wf2, h_wf2);
    cudaGetSymbolAddress((void**)&Rw, g_Rw);   cudaGetSymbolAddress((void**)&X1, g_X1);
    cudaGetSymbolAddress((void**)&bqkv, g_bqkv);
    cudaGetSymbolAddress((void**)&bd, g_bd);

    // ---- launch 1: 10 HxH weight packs (pw2/ow2 go K-concatenated into Wpd) ----
    PackB10 pb;
    auto set = [&](int i, const float* s, __half* d, int ldk, int koff, float sc) {
        pb.s[i] = s; pb.d[i] = d; pb.ldk[i] = ldk; pb.koff[i] = koff; pb.sc[i] = sc;
    };
    set(0, in[2],  W0,   HID, 0, 1.f);            // pw1
    set(1, in[4],  Wpd,  K2,  0, 1.f);            // pw2 -> Wpd[:, 0:2048]
    set(2, in[6],  W2,   HID, 0, 1.f);            // ow1
    set(3, in[8],  Wpd,  K2,  HID, -1.f);         // -ow2 -> Wpd[:, 2048:4096]
    set(4, in[10], W4,   HID, 0, 1.f);            // rw1
    set(5, in[12], W5,   HID, 0, 1.f);            // rw2
    set(6, in[14], Wqkv,            HID, 0, 1.f); // wq
    set(7, in[16], Wqkv + SZ_HH,    HID, 0, 1.f); // wk
    set(8, in[18], Wqkv + 2 * SZ_HH,HID, 0, 1.f); // wv
    set(9, in[20], W9,   HID, 0, 1.f);            // wo
    pack_bh10<<<dim3(HID / 32, HID / 64, 10), 256>>>(pb);

    // ---- launch 2: FFN weights, exact block count (8192 + 8192) ----
    PackBF pf; pf.s[0] = in[22]; pf.d[0] = Wf1; pf.s[1] = in[24]; pf.d[1] = Wf2;
    pack_bhffn<<<16384, 256>>>(pf);

    // ---- launch 3: inputs -> fp16, bias concat + bias diff ----
    PackMisc pm; pm.e = E; pm.o = Obs; pm.ep = Epk; pm.op = Opk;
    pm.b0 = in[15]; pm.b1 = in[17]; pm.b2 = in[19]; pm.bq = bqkv;
    pm.pb2 = in[5]; pm.ob2 = in[9]; pm.bd = bd;
    pack_misc<<<dim3(SZ_NH / 1024, 1, 3), 256>>>(pm);

    // 4: t0 = relu(E@pw1+pb1) -> TPw[:, 0:2048]  (ldc = 4096)
    G<1, true >(Epk, W0, in[3], nullptr, TPw, HID, HID, K2, 0);
    // 5: t1 = relu(Obs@ow1+ob1) -> TPw[:, 2048:4096]
    G<1, true >(Opk, W2, in[7], nullptr, TPw + HID, HID, HID, K2, 0);
    // 6: D = TPw @ [pw2; -ow2] + (pb2-ob2)  (K = 4096) -> Dp fp16
    G<0, true >(TPw, Wpd, bd, nullptr, Dp, HID, K2, HID, 0);
    // 7: t2 = relu(D@rw1+rb1) -> TP fp16
    G<1, true >(Dp, W4, in[11], nullptr, TP, HID, HID, HID, 0);
    // 8: R = t2@rw2+rb2 -> Dp (fp16; Dp free after launch 7)
    G<0, true >(TP, W5, in[13], nullptr, Dp, HID, HID, HID, 0);
    // 9: fused QKV projection (N = 6144) -> fp16
    G<0, true >(Epk, Wqkv, bqkv, nullptr, QKVh, QKVW, HID, QKVW, 0);
    attn_kernel<<<NTOK, 128>>>(QKVh, Dp, TP);                 // att (fp16)
    // t3 = E + att@wo + bo (fp32)
    G<4, false>(TP, W9, in[21], E, Rw, HID, HID, HID, HID);
    ln_kernel<true><<<NTOK, 256>>>(Rw, in[26], in[27], X1, TP);
    // FFN
    G<2, true >(TP, Wf1, in[23], nullptr, F1, FFN, HID, FFN, 0);
    G<4, false>(F1, Wf2, in[25], X1, Rw, HID, FFN, HID, HID);
    ln_kernel<false><<<NTOK, 256>>>(Rw, in[28], in[29], out, nullptr);
}